// round 6
// baseline (speedup 1.0000x reference)
#include <cuda_runtime.h>
#include <math.h>

#define NB 2
#define NA 512
#define NCGc 64
#define NF 128
#define NF3 384
#define NRBF 20
#define NCONV 3
#define NE 32768
#define BN 1024
#define CUT 5.0f
#define FPI 3.14159265358979323846f
#define WTP 1024
#define WTD 10.0f
#define WSP 4096
#define HN 16384   // NB*NCGc*NF
#define ACH 8      // atom chunks in contract

__device__ float g_h[BN*NF];
__device__ float g_v[BN*NF3];
__device__ float g_dh[BN*NF];
__device__ float g_dv[BN*NF3];
__device__ float g_phi[BN*NF3];
__device__ float g_uv[BN*NF3];
__device__ float g_vv[BN*NF3];
__device__ float g_a[BN*NF3];
__device__ float g_de[NE];
__device__ float g_ue[NE*3];
__device__ float g_dp[NB*NCGc*NA];
__device__ float g_up[NB*NCGc*NA*3];
__device__ float g_eb[WTP*NF];      // exp basis for wtab
__device__ float g_rb[WSP*32];      // rbf basis for wstab (zero-padded K=32)
__device__ float g_env[WSP];        // envelope per table point
__device__ float g_wtab[NCONV*WTP*NF3];   // w_c(d) table, d in [0,10]
__device__ float g_wstab[NCONV*WSP*NF3];  // w_s(d)*env(d) table, d in [0,5]

// ---- mega prologue: state init + geometry + table bases --------------------
__global__ void k_init0(const float* __restrict__ h, const float* __restrict__ Hin,
                        const float* __restrict__ xyz, const float* __restrict__ cg,
                        const int* __restrict__ nbr, float* __restrict__ out) {
    int i = blockIdx.x*blockDim.x + threadIdx.x;
    if (i < BN*NF3) { g_v[i] = 0.f; g_dv[i] = 0.f; }
    if (i < BN*NF)  { g_h[i] = h[i]; g_dh[i] = 0.f; }
    if (i < HN)     out[i] = Hin[i];
    if (i < HN*3)   out[HN + i] = 0.f;
    if (i < NE) {
        int b = nbr[3*i], ii = nbr[3*i+1], jj = nbr[3*i+2];
        float rx = xyz[(b*NA+ii)*3+0] - xyz[(b*NA+jj)*3+0];
        float ry = xyz[(b*NA+ii)*3+1] - xyz[(b*NA+jj)*3+1];
        float rz = xyz[(b*NA+ii)*3+2] - xyz[(b*NA+jj)*3+2];
        float d = sqrtf(rx*rx + ry*ry + rz*rz);
        g_de[i] = d;
        float inv = 1.f/d;
        g_ue[3*i+0] = rx*inv; g_ue[3*i+1] = ry*inv; g_ue[3*i+2] = rz*inv;
    }
    if (i < NB*NCGc*NA) {
        int a = i % NA; int bc = i / NA; int c = bc % NCGc; int b = bc / NCGc;
        float rx = xyz[(b*NA+a)*3+0] - cg[(b*NCGc+c)*3+0];
        float ry = xyz[(b*NA+a)*3+1] - cg[(b*NCGc+c)*3+1];
        float rz = xyz[(b*NA+a)*3+2] - cg[(b*NCGc+c)*3+2];
        float d = sqrtf(rx*rx + ry*ry + rz*rz);
        g_dp[i] = d;
        float inv = 1.f/d;
        g_up[3*i+0] = rx*inv; g_up[3*i+1] = ry*inv; g_up[3*i+2] = rz*inv;
    }
    if (i < WTP*NF) {   // exp basis
        int p = i >> 7, g = i & 127;
        float d = p * (WTD/(float)(WTP-1));
        float dd = d - g*(CUT/127.0f);
        g_eb[i] = expf(-dd*dd);
    }
    if (i < WSP*32) {   // rbf basis + env
        int p = i >> 5, n = i & 31;
        float d = p * (CUT/(float)(WSP-1));
        float de = fmaxf(d, 1e-6f);
        g_rb[i] = (n < NRBF) ? sinf((n+1)*(FPI/CUT)*de)/de : 0.f;
        if (n == 0) g_env[p] = 0.5f*(cosf(FPI*d/CUT) + 1.f);
    }
}

// ---- table build GEMM: C = (B @ W + bias) * env? --------------------------
// B[M x K] row-major basis; W rows [Kreal x NF3]; 64x64 tile, 256 thr, 4x4.
__global__ void k_tabgemm(const float* __restrict__ B, int K, int Kreal,
                          const float* __restrict__ W, int wstr,
                          const float* __restrict__ bias, int bstr,
                          const float* __restrict__ env,
                          float* __restrict__ Cbase, int cstr) {
    __shared__ float As[16][65];
    __shared__ float Ws[16][64];
    int t = blockIdx.z;
    int bm = blockIdx.y*64, bn = blockIdx.x*64;
    const float* Wt = W + (size_t)t*wstr;
    int tid = threadIdx.x;
    int tr = tid >> 4, tc = tid & 15;
    float acc[4][4];
    #pragma unroll
    for (int i = 0; i < 4; i++)
        #pragma unroll
        for (int j = 0; j < 4; j++) acc[i][j] = 0.f;
    for (int k0 = 0; k0 < K; k0 += 16) {
        for (int i = tid; i < 64*16; i += 256) {
            int kk = i & 15, r = i >> 4;
            As[kk][r] = B[(size_t)(bm+r)*K + k0 + kk];
        }
        for (int i = tid; i < 16*64; i += 256) {
            int kk = i >> 6, c = i & 63;
            int k = k0 + kk;
            Ws[kk][c] = (k < Kreal) ? Wt[(size_t)k*NF3 + bn + c] : 0.f;
        }
        __syncthreads();
        #pragma unroll
        for (int kk = 0; kk < 16; kk++) {
            float av[4], bv[4];
            #pragma unroll
            for (int i = 0; i < 4; i++) av[i] = As[kk][tr*4+i];
            #pragma unroll
            for (int j = 0; j < 4; j++) bv[j] = Ws[kk][tc*4+j];
            #pragma unroll
            for (int i = 0; i < 4; i++)
                #pragma unroll
                for (int j = 0; j < 4; j++) acc[i][j] += av[i]*bv[j];
        }
        __syncthreads();
    }
    float* C = Cbase + (size_t)t*cstr;
    #pragma unroll
    for (int i = 0; i < 4; i++) {
        int r = bm + tr*4 + i;
        float ev = env ? env[r] : 1.f;
        #pragma unroll
        for (int j = 0; j < 4; j++) {
            int c = bn + tc*4 + j;
            C[(size_t)r*NF3 + c] = (acc[i][j] + bias[(size_t)t*bstr + c]) * ev;
        }
    }
}

// ---- fused MLP: C[M x 384] = silu(A @ W1 + b1) @ W2 + b2 ------------------
// mode 0: A = g_h (K=128). mode 1: A = [h | vnorm] (K=256, norm on the fly).
// Block: 64 rows x 64 out-cols, 256 threads; t1 stays in smem.
#define MLP_SMEM ((16*65 + 16*128 + 64*129 + 128*64) * 4)
__global__ void k_mlp(int mode,
                      const float* __restrict__ W1, const float* __restrict__ b1,
                      const float* __restrict__ W2, const float* __restrict__ b2,
                      float* __restrict__ C) {
    extern __shared__ float sm[];
    float* As  = sm;                       // [16][65]
    float* W1s = sm + 16*65;               // [16][128]
    float* t1s = W1s + 16*128;             // [64][129]
    float* W2s = t1s + 64*129;             // [128][64]
    int row0 = blockIdx.y*64;
    int col0 = blockIdx.x*64;
    int tid = threadIdx.x;
    int ty = tid >> 4;       // 0..15
    int tx = tid & 15;       // 0..15
    int K = mode ? 256 : 128;

    float acc1[4][8];
    #pragma unroll
    for (int i = 0; i < 4; i++)
        #pragma unroll
        for (int j = 0; j < 8; j++) acc1[i][j] = 0.f;

    int nk = K >> 4;
    for (int it = 0; it < nk; it++) {
        int k0 = it*16;
        #pragma unroll
        for (int p = 0; p < 4; p++) {
            int idx = tid + p*256;
            int kk = idx & 15, r = idx >> 4;
            int k = k0 + kk, row = row0 + r;
            float v;
            if (k < 128) {
                v = g_h[(size_t)row*NF + k];
            } else {
                int g = k - 128;
                float x = g_vv[(size_t)row*NF3 + g*3+0];
                float y = g_vv[(size_t)row*NF3 + g*3+1];
                float z = g_vv[(size_t)row*NF3 + g*3+2];
                v = sqrtf(x*x + y*y + z*z + 1e-15f);
            }
            As[kk*65 + r] = v;
        }
        #pragma unroll
        for (int p = 0; p < 8; p++) {
            int idx = tid + p*256;
            int kk = idx >> 7, c = idx & 127;
            W1s[kk*128 + c] = W1[(size_t)(k0+kk)*128 + c];
        }
        if (it < 8) {
            #pragma unroll
            for (int p = 0; p < 4; p++) {
                int idx = tid + p*256;
                int kk = it*16 + (idx >> 6), c = idx & 63;
                W2s[kk*64 + c] = W2[(size_t)kk*NF3 + col0 + c];
            }
        }
        __syncthreads();
        #pragma unroll
        for (int kk = 0; kk < 16; kk++) {
            float a[4], w[8];
            #pragma unroll
            for (int i = 0; i < 4; i++) a[i] = As[kk*65 + ty + 16*i];
            #pragma unroll
            for (int j = 0; j < 8; j++) w[j] = W1s[kk*128 + tx + 16*j];
            #pragma unroll
            for (int i = 0; i < 4; i++)
                #pragma unroll
                for (int j = 0; j < 8; j++) acc1[i][j] += a[i]*w[j];
        }
        __syncthreads();
    }
    #pragma unroll
    for (int i = 0; i < 4; i++)
        #pragma unroll
        for (int j = 0; j < 8; j++) {
            int c = tx + 16*j;
            float v = acc1[i][j] + b1[c];
            v = v / (1.f + __expf(-v));
            t1s[(ty + 16*i)*129 + c] = v;
        }
    __syncthreads();

    float acc2[4][4];
    #pragma unroll
    for (int i = 0; i < 4; i++)
        #pragma unroll
        for (int j = 0; j < 4; j++) acc2[i][j] = 0.f;
    #pragma unroll 4
    for (int kk = 0; kk < 128; kk++) {
        float a2[4], w2v[4];
        #pragma unroll
        for (int i = 0; i < 4; i++) a2[i] = t1s[(ty + 16*i)*129 + kk];
        #pragma unroll
        for (int j = 0; j < 4; j++) w2v[j] = W2s[kk*64 + tx + 16*j];
        #pragma unroll
        for (int i = 0; i < 4; i++)
            #pragma unroll
            for (int j = 0; j < 4; j++) acc2[i][j] += a2[i]*w2v[j];
    }
    #pragma unroll
    for (int i = 0; i < 4; i++) {
        int r = row0 + ty + 16*i;
        #pragma unroll
        for (int j = 0; j < 4; j++) {
            int c = col0 + tx + 16*j;
            C[(size_t)r*NF3 + c] = acc2[i][j] + b2[c];
        }
    }
}

// batched uv/vv GEMM: blockIdx.z = component e, x selects {n-tile, U/V}
__global__ void k_gemm_uv(const float* __restrict__ U, const float* __restrict__ V) {
    __shared__ float As[16][65];
    __shared__ float Ws[16][64];
    int e = blockIdx.z;
    int which = blockIdx.x >> 1;
    int bn = (blockIdx.x & 1)*64;
    int bm = blockIdx.y*64;
    const float* A = g_v + e;
    const float* W = which ? V : U;
    float* C = (which ? g_vv : g_uv) + e;
    int tid = threadIdx.x;
    int tr = tid >> 4, tc = tid & 15;
    float acc[4][4];
    #pragma unroll
    for (int i = 0; i < 4; i++)
        #pragma unroll
        for (int j = 0; j < 4; j++) acc[i][j] = 0.f;
    for (int k0 = 0; k0 < NF; k0 += 16) {
        for (int i = tid; i < 64*16; i += 256) {
            int kk = i & 15, r = i >> 4;
            As[kk][r] = A[(size_t)(bm+r)*NF3 + (size_t)(k0+kk)*3];
        }
        for (int i = tid; i < 16*64; i += 256) {
            int kk = i >> 6, c = i & 63;
            Ws[kk][c] = W[(size_t)(k0+kk)*NF + bn + c];
        }
        __syncthreads();
        #pragma unroll
        for (int kk = 0; kk < 16; kk++) {
            float av[4], bv[4];
            #pragma unroll
            for (int i = 0; i < 4; i++) av[i] = As[kk][tr*4+i];
            #pragma unroll
            for (int j = 0; j < 4; j++) bv[j] = Ws[kk][tc*4+j];
            #pragma unroll
            for (int i = 0; i < 4; i++)
                #pragma unroll
                for (int j = 0; j < 4; j++) acc[i][j] += av[i]*bv[j];
        }
        __syncthreads();
    }
    #pragma unroll
    for (int i = 0; i < 4; i++) {
        int r = bm + tr*4 + i;
        #pragma unroll
        for (int j = 0; j < 4; j++) {
            int c = bn + tc*4 + j;
            C[(size_t)r*NF3 + (size_t)c*3] = acc[i][j];
        }
    }
}

// edge messages via wstab lerp; 2 edges per 256-thread block
__global__ void k_edge(const int* __restrict__ nbr, const float* __restrict__ wst) {
    int e = blockIdx.x*2 + (threadIdx.x >> 7);
    int f = threadIdx.x & 127;
    float d = g_de[e];
    if (d >= CUT) return;
    float x = fminf(d * ((float)(WSP-1)/CUT), (float)(WSP-1));
    int p0 = min((int)x, WSP-2);
    float fr = x - (float)p0;
    const float* r0 = wst + (size_t)p0*NF3;
    const float* r1 = r0 + NF3;
    float ws0 = r0[f]      + fr*(r1[f]      - r0[f]);
    float ws1 = r0[NF+f]   + fr*(r1[NF+f]   - r0[NF+f]);
    float ws2 = r0[2*NF+f] + fr*(r1[2*NF+f] - r0[2*NF+f]);
    int b = nbr[3*e], i = nbr[3*e+1], j = nbr[3*e+2];
    int pi = b*NA + i, pj = b*NA + j;
    float i0 = ws0*g_phi[pj*NF3 + f];
    float i1 = ws1*g_phi[pj*NF3 + NF + f];
    float i2 = ws2*g_phi[pj*NF3 + 2*NF + f];
    atomicAdd(&g_dh[pi*NF + f], i1);
    float ux = g_ue[3*e], uy = g_ue[3*e+1], uz = g_ue[3*e+2];
    int vb = pj*NF3 + f*3, ob = pi*NF3 + f*3;
    atomicAdd(&g_dv[ob+0], i2*ux + i0*g_v[vb+0]);
    atomicAdd(&g_dv[ob+1], i2*uy + i0*g_v[vb+1]);
    atomicAdd(&g_dv[ob+2], i2*uz + i0*g_v[vb+2]);
}

__global__ void k_apply_msg() {
    int i = blockIdx.x*blockDim.x + threadIdx.x;
    if (i >= BN*NF3) return;
    g_v[i] += 0.5f*g_dv[i]; g_dv[i] = 0.f;
    if (i < BN*NF) { g_h[i] += 0.5f*g_dh[i]; g_dh[i] = 0.f; }
}

__global__ void k_apply_upd() {
    int i = blockIdx.x*blockDim.x + threadIdx.x;
    if (i >= BN*NF) return;
    int n = i >> 7, g = i & 127;
    float u0 = g_uv[n*NF3+g*3+0], u1 = g_uv[n*NF3+g*3+1], u2 = g_uv[n*NF3+g*3+2];
    float w0 = g_vv[n*NF3+g*3+0], w1 = g_vv[n*NF3+g*3+1], w2 = g_vv[n*NF3+g*3+2];
    float dot = u0*w0 + u1*w1 + u2*w2;
    float a0 = g_a[n*NF3 + g];
    float a1 = g_a[n*NF3 + NF + g];
    float a2 = g_a[n*NF3 + 2*NF + g];
    g_h[i] += 0.5f*(dot*a1 + a2);
    g_v[n*NF3+g*3+0] += 0.5f*a0*u0;
    g_v[n*NF3+g*3+1] += 0.5f*a0*u1;
    g_v[n*NF3+g*3+2] += 0.5f*a0*u2;
}

__global__ void k_contract(const float* __restrict__ assign,
                           const float* __restrict__ wt, float* __restrict__ out) {
    int c = blockIdx.x, b = blockIdx.y, f = threadIdx.x;
    int a0 = blockIdx.z * (NA/ACH);
    float accH = 0.f, aV0 = 0.f, aV1 = 0.f, aV2 = 0.f;
    int pc = (b*NCGc + c)*NA;
    #pragma unroll 2
    for (int a = a0; a < a0 + NA/ACH; a++) {
        int pa = b*NA + a;
        float s = __ldg(&assign[pa*NCGc + c]);
        float d = g_dp[pc + a];
        float x = fminf(d * ((WTP-1)/WTD), (float)(WTP-1));
        int p0 = min((int)x, WTP-2);
        float fr = x - (float)p0;
        const float* r0 = wt + (size_t)p0*NF3 + 3*f;
        float w0 = r0[0] + fr*(r0[NF3+0] - r0[0]);
        float w1 = r0[1] + fr*(r0[NF3+1] - r0[1]);
        float w2 = r0[2] + fr*(r0[NF3+2] - r0[2]);
        const float* ph = g_phi + (size_t)pa*NF3 + 3*f;
        const float* vv = g_v   + (size_t)pa*NF3 + 3*f;
        float fw0 = w0*ph[0], fw1 = w1*ph[1], fw2 = w2*ph[2];
        float ux = g_up[(pc+a)*3+0], uy = g_up[(pc+a)*3+1], uz = g_up[(pc+a)*3+2];
        accH += s*fw1;
        aV0  += s*(fw2*ux + fw0*vv[0]);
        aV1  += s*(fw2*uy + fw0*vv[1]);
        aV2  += s*(fw2*uz + fw0*vv[2]);
    }
    int hi = (b*NCGc + c)*NF + f;
    atomicAdd(&out[hi], accH);
    int vo = HN + hi*3;
    atomicAdd(&out[vo+0], aV0);
    atomicAdd(&out[vo+1], aV1);
    atomicAdd(&out[vo+2], aV2);
}

static inline float* sym(const void* s) {
    void* p = nullptr;
    cudaGetSymbolAddress(&p, s);
    return (float*)p;
}

extern "C" void kernel_launch(void* const* d_in, const int* in_sizes, int n_in,
                              void* d_out, int out_size) {
    const float* h      = (const float*)d_in[0];
    const float* Hin    = (const float*)d_in[1];
    const float* xyz    = (const float*)d_in[2];
    const float* cgxyz  = (const float*)d_in[3];
    const float* assign = (const float*)d_in[4];
    const int*   nbr    = (const int*)d_in[6];
    const float* mW1 = (const float*)d_in[7];
    const float* mb1 = (const float*)d_in[8];
    const float* mW2 = (const float*)d_in[9];
    const float* mb2 = (const float*)d_in[10];
    const float* mWe = (const float*)d_in[11];
    const float* mbe = (const float*)d_in[12];
    const float* uU  = (const float*)d_in[13];
    const float* uV  = (const float*)d_in[14];
    const float* uW1 = (const float*)d_in[15];
    const float* ub1 = (const float*)d_in[16];
    const float* uW2 = (const float*)d_in[17];
    const float* ub2 = (const float*)d_in[18];
    const float* cWf = (const float*)d_in[19];
    const float* cbf = (const float*)d_in[20];
    const float* cW1 = (const float*)d_in[21];
    const float* cb1 = (const float*)d_in[22];
    const float* cW2 = (const float*)d_in[23];
    const float* cb2 = (const float*)d_in[24];
    float* out = (float*)d_out;

    float *pphi = sym(g_phi), *pa = sym(g_a);
    float *pwt = sym(g_wtab), *pws = sym(g_wstab);
    float *peb = sym(g_eb), *prb = sym(g_rb), *penv = sym(g_env);

    cudaFuncSetAttribute(k_mlp, cudaFuncAttributeMaxDynamicSharedMemorySize, MLP_SMEM);

    k_init0<<<1536, 256>>>(h, Hin, xyz, cgxyz, nbr, out);
    k_tabgemm<<<dim3(6,WTP/64,NCONV),256>>>(peb, NF, NF, cWf, NF*NF3, cbf, NF3,
                                            nullptr, pwt, WTP*NF3);
    k_tabgemm<<<dim3(6,WSP/64,NCONV),256>>>(prb, 32, NRBF, mWe, NRBF*NF3, mbe, NF3,
                                            penv, pws, WSP*NF3);

    for (int t = 0; t < NCONV; t++) {
        // message phase: fused MLP (h -> phi)
        k_mlp<<<dim3(6,16),256,MLP_SMEM>>>(0, mW1+t*NF*NF, mb1+t*NF,
                                           mW2+t*NF*NF3, mb2+t*NF3, pphi);
        k_edge<<<NE/2,256>>>(nbr, pws + (size_t)t*WSP*NF3);
        k_apply_msg<<<1536,256>>>();
        // update phase
        k_gemm_uv<<<dim3(4,16,3),256>>>(uU+t*NF*NF, uV+t*NF*NF);
        k_mlp<<<dim3(6,16),256,MLP_SMEM>>>(1, uW1+t*2*NF*NF, ub1+t*NF,
                                           uW2+t*NF*NF3, ub2+t*NF3, pa);
        k_apply_upd<<<512,256>>>();
        // contraction phase
        k_mlp<<<dim3(6,16),256,MLP_SMEM>>>(0, cW1+t*NF*NF, cb1+t*NF,
                                           cW2+t*NF*NF3, cb2+t*NF3, pphi);
        k_contract<<<dim3(NCGc,NB,ACH),128>>>(assign, pwt + (size_t)t*WTP*NF3, out);
    }
}